// round 3
// baseline (speedup 1.0000x reference)
#include <cuda_runtime.h>
#include <math.h>

#define BB 64
#define LL 20
#define HH 300
#define PP 8
#define NND 32768
#define EED 262144
#define CCD 2048
#define CE 2049
#define OUTD 1845
#define H4 1200
#define K2 2400
#define NPG 512
#define ML (BB*LL)

static __device__ float g_qw[ML*HH];
static __device__ float g_logits[ML*CE];
static __device__ float g_vocab[CE*HH];
static __device__ float g_tagged[ML*HH];
static __device__ float g_xw[ML*H4];
static __device__ float g_WihT[HH*H4];
static __device__ float g_WhhT[HH*H4];
static __device__ float g_rWihT[HH*HH];
static __device__ float g_rWhhT[HH*HH];
static __device__ float g_fc1T[600*600];
static __device__ float g_fc2T[600*OUTD];
static __device__ float g_h[BB*HH];
static __device__ float g_c[BB*HH];
static __device__ float g_hx[BB*HH];
static __device__ float g_ew[BB*HH];
static __device__ float g_hidden[BB*4*HH];
static __device__ float g_instr[BB*4*HH];
static __device__ float g_vb[BB*K2];
static __device__ float g_psim[BB*9];
static __device__ float g_dist[NND];
static __device__ float g_nsl[NND];
static __device__ float g_nrl[NND];
static __device__ float g_agg[BB*HH];
static __device__ float g_feat1[BB*600];
static __device__ float g_cnt[BB];

__device__ __forceinline__ float sigf(float x){ return 1.f/(1.f+expf(-x)); }
__device__ __forceinline__ float eluf(float x){ return x > 0.f ? x : expm1f(x); }

__global__ void transpose_k(const float* __restrict__ src, float* __restrict__ dst, int R, int C) {
    int idx = blockIdx.x*blockDim.x + threadIdx.x;
    if (idx < R*C) { int r = idx / C, c = idx % C; dst[c*R + r] = src[idx]; }
}

__global__ void copy_vocab_k(const float* __restrict__ cv, const float* __restrict__ demb) {
    int idx = blockIdx.x*blockDim.x + threadIdx.x;
    if (idx < CE*HH) { int c = idx / HH, h = idx % HH; g_vocab[idx] = (c < CCD) ? cv[idx] : demb[h]; }
}

__global__ void init_zero_k() {
    int idx = blockIdx.x*blockDim.x + threadIdx.x;
    if (idx < BB*HH) { g_h[idx]=0.f; g_c[idx]=0.f; g_hx[idx]=0.f; g_agg[idx]=0.f; }
    if (idx < BB) g_cnt[idx]=0.f;
}

__global__ void count_k(const int* __restrict__ nidx) {
    int n = blockIdx.x*blockDim.x + threadIdx.x;
    if (n < NND) atomicAdd(&g_cnt[nidx[n]], 1.f);
}

__global__ void dist_init_k(const int* __restrict__ nidx) {
    int n = blockIdx.x*blockDim.x + threadIdx.x;
    if (n < NND) g_dist[n] = 1.f / g_cnt[nidx[n]];
}

__global__ void zero_nl_k() {
    int n = blockIdx.x*blockDim.x + threadIdx.x;
    if (n < NND) { g_nsl[n]=0.f; g_nrl[n]=0.f; }
}

// generic 64x64 tiled GEMM, 4x4 micro-tile. TB=1 -> C = A @ B^T (B is Nc x K)
template<int TB>
__global__ void gemm_t(const float* __restrict__ A, const float* __restrict__ Bm,
                       float* __restrict__ C, int M, int Nc, int K,
                       int lda, int ldb, int ldc) {
    __shared__ float As[64][17];
    __shared__ float Bs[16][65];
    int tid = threadIdx.x;
    int tx = tid & 15, ty = tid >> 4;
    int row0 = blockIdx.y * 64, c0 = blockIdx.x * 64;
    float acc[4][4];
    #pragma unroll
    for (int i=0;i<4;i++) for (int j=0;j<4;j++) acc[i][j]=0.f;
    for (int k0 = 0; k0 < K; k0 += 16) {
        #pragma unroll
        for (int i = 0; i < 4; i++) {
            int e = tid + 256*i;
            int r = e >> 4, kk = e & 15;
            As[r][kk] = (k0+kk < K) ? A[(row0+r)*lda + k0+kk] : 0.f;
            if (TB) {
                int cc = e >> 4, kb = e & 15;
                Bs[kb][cc] = (k0+kb < K && c0+cc < Nc) ? Bm[(c0+cc)*ldb + k0+kb] : 0.f;
            } else {
                int cc = e & 63, kb = e >> 6;
                Bs[kb][cc] = (k0+kb < K && c0+cc < Nc) ? Bm[(k0+kb)*ldb + c0+cc] : 0.f;
            }
        }
        __syncthreads();
        #pragma unroll
        for (int kk = 0; kk < 16; kk++) {
            float ra[4], rb[4];
            #pragma unroll
            for (int i=0;i<4;i++) ra[i] = As[ty*4+i][kk];
            #pragma unroll
            for (int j=0;j<4;j++) rb[j] = Bs[kk][tx*4+j];
            #pragma unroll
            for (int i=0;i<4;i++) for (int j=0;j<4;j++) acc[i][j] += ra[i]*rb[j];
        }
        __syncthreads();
    }
    #pragma unroll
    for (int i=0;i<4;i++)
        #pragma unroll
        for (int j=0;j<4;j++) {
            int c = c0 + tx*4 + j;
            if (c < Nc) C[(row0+ty*4+i)*ldc + c] = acc[i][j];
        }
}

__global__ void softmax_rows_k() {
    __shared__ float red[256];
    int m = blockIdx.x, t = threadIdx.x;
    float* p = &g_logits[m*CE];
    float v = -1e30f;
    for (int i = t; i < CE; i += 256) v = fmaxf(v, p[i]);
    red[t] = v; __syncthreads();
    for (int s = 128; s > 0; s >>= 1) { if (t < s) red[t] = fmaxf(red[t], red[t+s]); __syncthreads(); }
    float mx = red[0]; __syncthreads();
    float sum = 0.f;
    for (int i = t; i < CE; i += 256) { float e = expf(p[i]-mx); p[i] = e; sum += e; }
    red[t] = sum; __syncthreads();
    for (int s = 128; s > 0; s >>= 1) { if (t < s) red[t] += red[t+s]; __syncthreads(); }
    float inv = 1.f / red[0];
    for (int i = t; i < CE; i += 256) p[i] *= inv;
}

__global__ void tagged_adj_k(const float* __restrict__ questions) {
    int idx = blockIdx.x*blockDim.x + threadIdx.x;
    if (idx < ML*HH) g_tagged[idx] += g_logits[(idx/HH)*CE + CCD] * questions[idx];
}

__global__ void lstm_step_k(const float* __restrict__ bih, const float* __restrict__ bhh, int t) {
    int b = blockIdx.x, tid = threadIdx.x;   // 600 threads
    __shared__ float hs[HH];
    __shared__ float z[H4];
    if (tid < HH) hs[tid] = g_h[b*HH + tid];
    __syncthreads();
    for (int j = tid; j < H4; j += 600) {
        float a = g_xw[(b*LL + t)*H4 + j] + bih[j] + bhh[j];
        #pragma unroll 4
        for (int h = 0; h < HH; h++) a += g_WhhT[h*H4 + j] * hs[h];
        z[j] = a;
    }
    __syncthreads();
    if (tid < HH) {
        float iv = sigf(z[tid]), fv = sigf(z[HH+tid]);
        float gv = tanhf(z[2*HH+tid]), ov = sigf(z[3*HH+tid]);
        float c = fv * g_c[b*HH+tid] + iv*gv;
        g_c[b*HH+tid] = c;
        g_h[b*HH+tid] = ov * tanhf(c);
    }
}

__global__ void rnn_ew_k() {
    int b = blockIdx.x, k = threadIdx.x;     // 300 threads
    __shared__ float es[HH];
    es[k] = g_h[b*HH + k];
    __syncthreads();
    float a = 0.f;
    #pragma unroll 4
    for (int h = 0; h < HH; h++) a += g_rWihT[h*HH + k] * es[h];
    g_ew[b*HH + k] = a;
}

__global__ void rnn_step_k(const float* __restrict__ rbih, const float* __restrict__ rbhh, int s) {
    int b = blockIdx.x, k = threadIdx.x;
    __shared__ float hs[HH];
    hs[k] = g_hx[b*HH + k];
    __syncthreads();
    float a = g_ew[b*HH + k] + rbih[k] + rbhh[k];
    #pragma unroll 4
    for (int h = 0; h < HH; h++) a += g_rWhhT[h*HH + k] * hs[h];
    a = fmaxf(a, 0.f);
    g_hx[b*HH + k] = a;
    g_hidden[(b*4 + s)*HH + k] = a;
}

__global__ void attn_k() {
    int b = blockIdx.x, ii = blockIdx.y, tid = threadIdx.x;   // 128 threads
    __shared__ float hid[HH];
    __shared__ float sc[LL];
    for (int k = tid; k < HH; k += 128) hid[k] = g_hidden[(b*4+ii)*HH + k];
    __syncthreads();
    int warp = tid >> 5, lane = tid & 31;
    for (int l = warp; l < LL; l += 4) {
        float a = 0.f;
        for (int h = lane; h < HH; h += 32) a += hid[h] * g_tagged[(b*LL+l)*HH + h];
        #pragma unroll
        for (int o = 16; o > 0; o >>= 1) a += __shfl_xor_sync(0xffffffffu, a, o);
        if (lane == 0) sc[l] = a;
    }
    __syncthreads();
    if (tid == 0) {
        float mx = -1e30f;
        for (int l = 0; l < LL; l++) mx = fmaxf(mx, sc[l]);
        float sum = 0.f;
        for (int l = 0; l < LL; l++) { sc[l] = expf(sc[l]-mx); sum += sc[l]; }
        for (int l = 0; l < LL; l++) sc[l] /= sum;
    }
    __syncthreads();
    for (int k = tid; k < HH; k += 128) {
        float a = 0.f;
        #pragma unroll
        for (int l = 0; l < LL; l++) a += sc[l] * g_tagged[(b*LL+l)*HH + k];
        g_instr[(b*4+ii)*HH + k] = a;
    }
}

__global__ void psim_k(const float* __restrict__ prop, int step) {
    __shared__ float s[BB*9];
    int tid = threadIdx.x;                  // 576 threads, 1 block
    int b = tid / 9, p = tid % 9;
    const float* ins = &g_instr[(b*4+step)*HH];
    float a = 0.f;
    for (int h = 0; h < HH; h++) a += ins[h] * prop[p*HH + h];
    s[tid] = a;
    __syncthreads();
    if (p == 0) {
        float mx = -1e30f;
        for (int q = 0; q < 9; q++) mx = fmaxf(mx, s[b*9+q]);
        float e[9], sum = 0.f;
        for (int q = 0; q < 9; q++) { e[q] = expf(s[b*9+q]-mx); sum += e[q]; }
        for (int q = 0; q < 9; q++) g_psim[b*9+q] = e[q]/sum;
    }
}

__global__ void vb_k(int step) {
    int b = blockIdx.x;
    for (int j = threadIdx.x; j < K2; j += 256)
        g_vb[b*K2 + j] = g_psim[b*9 + j/HH] * g_instr[(b*4+step)*HH + j%HH];
}

// node scores GEMM: 128x64 tile, 8x8 micro; fused elu + w_ns dot + atomic
__global__ void node_gemm_k(const float* __restrict__ attrs, const int* __restrict__ nidx,
                            const float* __restrict__ Wp, const float* __restrict__ wns) {
    __shared__ float As[128][17];
    __shared__ float Bs[16][65];
    __shared__ int rb[128];
    int tid = threadIdx.x;                  // 128
    int row0 = blockIdx.y * 128, c0 = blockIdx.x * 64;
    rb[tid] = nidx[row0 + tid];
    __syncthreads();
    float acc[8][8];
    #pragma unroll
    for (int i=0;i<8;i++) for (int j=0;j<8;j++) acc[i][j]=0.f;
    int tr = tid >> 3, tc = tid & 7;
    for (int k0 = 0; k0 < K2; k0 += 16) {
        #pragma unroll
        for (int i = 0; i < 16; i++) {
            int e = tid + 128*i;
            int r = e >> 4, kk = e & 15;
            int gk = k0 + kk;
            As[r][kk] = attrs[(row0+r)*K2 + gk] * g_vb[rb[r]*K2 + gk];
        }
        #pragma unroll
        for (int i = 0; i < 8; i++) {
            int e = tid + 128*i;
            int cc = e & 63, kb = e >> 6;
            int c = c0 + cc;
            Bs[kb][cc] = (c < HH) ? Wp[(k0+kb)*HH + c] : 0.f;
        }
        __syncthreads();
        #pragma unroll
        for (int kk = 0; kk < 16; kk++) {
            float ra[8], rv[8];
            #pragma unroll
            for (int i=0;i<8;i++) ra[i] = As[tr*8+i][kk];
            #pragma unroll
            for (int j=0;j<8;j++) rv[j] = Bs[kk][tc*8+j];
            #pragma unroll
            for (int i=0;i<8;i++) for (int j=0;j<8;j++) acc[i][j] += ra[i]*rv[j];
        }
        __syncthreads();
    }
    #pragma unroll
    for (int i = 0; i < 8; i++) {
        float part = 0.f;
        #pragma unroll
        for (int j = 0; j < 8; j++) {
            int c = c0 + tc*8 + j;
            float v = acc[i][j];
            v = v > 0.f ? v : expm1f(v);
            if (c < HH) part += v * wns[c];
        }
        part += __shfl_xor_sync(0xffffffffu, part, 1);
        part += __shfl_xor_sync(0xffffffffu, part, 2);
        part += __shfl_xor_sync(0xffffffffu, part, 4);
        if (tc == 0) atomicAdd(&g_nsl[row0 + tr*8 + i], part);
    }
}

// edge scores GEMM: fused elu + w_rs dot + dist[src] scale + scatter to dst
__global__ void edge_gemm_k(const float* __restrict__ eattrs, const int* __restrict__ ebatch,
                            const int* __restrict__ esrc, const int* __restrict__ edst,
                            const float* __restrict__ We, const float* __restrict__ wrs, int step) {
    __shared__ float As[128][17];
    __shared__ float Bs[16][65];
    __shared__ int rb[128];
    int tid = threadIdx.x;
    int row0 = blockIdx.y * 128, c0 = blockIdx.x * 64;
    rb[tid] = ebatch[row0 + tid];
    __syncthreads();
    float acc[8][8];
    #pragma unroll
    for (int i=0;i<8;i++) for (int j=0;j<8;j++) acc[i][j]=0.f;
    int tr = tid >> 3, tc = tid & 7;
    for (int k0 = 0; k0 < HH; k0 += 16) {
        #pragma unroll
        for (int i = 0; i < 16; i++) {
            int e = tid + 128*i;
            int r = e >> 4, kk = e & 15;
            int gk = k0 + kk;
            As[r][kk] = (gk < HH) ? eattrs[(row0+r)*HH + gk] * g_instr[(rb[r]*4+step)*HH + gk] : 0.f;
        }
        #pragma unroll
        for (int i = 0; i < 8; i++) {
            int e = tid + 128*i;
            int cc = e & 63, kb = e >> 6;
            int c = c0 + cc;
            Bs[kb][cc] = (k0+kb < HH && c < HH) ? We[(k0+kb)*HH + c] : 0.f;
        }
        __syncthreads();
        #pragma unroll
        for (int kk = 0; kk < 16; kk++) {
            float ra[8], rv[8];
            #pragma unroll
            for (int i=0;i<8;i++) ra[i] = As[tr*8+i][kk];
            #pragma unroll
            for (int j=0;j<8;j++) rv[j] = Bs[kk][tc*8+j];
            #pragma unroll
            for (int i=0;i<8;i++) for (int j=0;j<8;j++) acc[i][j] += ra[i]*rv[j];
        }
        __syncthreads();
    }
    #pragma unroll
    for (int i = 0; i < 8; i++) {
        float part = 0.f;
        #pragma unroll
        for (int j = 0; j < 8; j++) {
            int c = c0 + tc*8 + j;
            float v = acc[i][j];
            v = v > 0.f ? v : expm1f(v);
            if (c < HH) part += v * wrs[c];
        }
        part += __shfl_xor_sync(0xffffffffu, part, 1);
        part += __shfl_xor_sync(0xffffffffu, part, 2);
        part += __shfl_xor_sync(0xffffffffu, part, 4);
        if (tc == 0) {
            int e = row0 + tr*8 + i;
            atomicAdd(&g_nrl[edst[e]], g_dist[esrc[e]] * part);
        }
    }
}

__global__ void seg_softmax_k() {
    __shared__ float red[NPG];
    int b = blockIdx.x, t = threadIdx.x;   // 512 threads
    int n = b*NPG + t;
    float v1 = g_nsl[n], v2 = g_nrl[n];
    red[t] = v1; __syncthreads();
    for (int s = 256; s > 0; s >>= 1) { if (t < s) red[t] = fmaxf(red[t], red[t+s]); __syncthreads(); }
    float m1 = red[0]; __syncthreads();
    float e1 = expf(v1 - m1);
    red[t] = e1; __syncthreads();
    for (int s = 256; s > 0; s >>= 1) { if (t < s) red[t] += red[t+s]; __syncthreads(); }
    float s1 = red[0]; __syncthreads();
    red[t] = v2; __syncthreads();
    for (int s = 256; s > 0; s >>= 1) { if (t < s) red[t] = fmaxf(red[t], red[t+s]); __syncthreads(); }
    float m2 = red[0]; __syncthreads();
    float e2 = expf(v2 - m2);
    red[t] = e2; __syncthreads();
    for (int s = 256; s > 0; s >>= 1) { if (t < s) red[t] += red[t+s]; __syncthreads(); }
    float s2 = red[0]; __syncthreads();
    float rs = g_psim[b*9 + 8];
    g_dist[n] = rs * (e2/s2) + (1.f - rs) * (e1/s1);
}

__global__ void agg_k(const float* __restrict__ attrs) {
    int b = blockIdx.x, ch = blockIdx.y, h = threadIdx.x;  // 300 threads, y=8 chunks
    __shared__ float np[8];
    if (h < 8) np[h] = g_psim[b*9 + h];
    __syncthreads();
    float acc = 0.f;
    int nbase = b*NPG + ch*(NPG/8);
    for (int nn = 0; nn < NPG/8; nn++) {
        int n = nbase + nn;
        float d = g_dist[n], w = 0.f;
        #pragma unroll
        for (int p = 0; p < 8; p++) w += np[p] * attrs[(n*PP + p)*HH + h];
        acc += d * w;
    }
    atomicAdd(&g_agg[b*HH + h], acc);
}

__global__ void fc1_k(const float* __restrict__ fc1b) {
    int b = blockIdx.x, j = threadIdx.x;   // 600 threads
    __shared__ float fs[600];
    fs[j] = (j < HH) ? g_h[b*HH + j] : g_agg[b*HH + (j - HH)];
    __syncthreads();
    float a = fc1b[j];
    #pragma unroll 4
    for (int k = 0; k < 600; k++) a += g_fc1T[k*600 + j] * fs[k];
    g_feat1[b*600 + j] = eluf(a);
}

__global__ void fc2_k(const float* __restrict__ fc2b, float* __restrict__ out) {
    int b = blockIdx.x, t = threadIdx.x;   // 256 threads, y=8
    __shared__ float f1[600];
    for (int k = t; k < 600; k += 256) f1[k] = g_feat1[b*600 + k];
    __syncthreads();
    int o = blockIdx.y*256 + t;
    if (o < OUTD) {
        float a = fc2b[o];
        #pragma unroll 4
        for (int k = 0; k < 600; k++) a += g_fc2T[k*OUTD + o] * f1[k];
        out[b*OUTD + o] = a;
    }
}

extern "C" void kernel_launch(void* const* d_in, const int* in_sizes, int n_in,
                              void* d_out, int out_size) {
    (void)in_sizes; (void)n_in; (void)out_size;
    const float* questions  = (const float*)d_in[0];
    const float* cvocab     = (const float*)d_in[1];
    const float* prop       = (const float*)d_in[2];
    const float* node_attrs = (const float*)d_in[3];
    const float* edge_attrs = (const float*)d_in[4];
    const float* w_tag      = (const float*)d_in[5];
    const float* demb       = (const float*)d_in[6];
    const float* lstm_Wih   = (const float*)d_in[7];
    const float* lstm_Whh   = (const float*)d_in[8];
    const float* lstm_bih   = (const float*)d_in[9];
    const float* lstm_bhh   = (const float*)d_in[10];
    const float* rnn_Wih    = (const float*)d_in[11];
    const float* rnn_Whh    = (const float*)d_in[12];
    const float* rnn_bih    = (const float*)d_in[13];
    const float* rnn_bhh    = (const float*)d_in[14];
    const float* Wp         = (const float*)d_in[15];
    const float* We         = (const float*)d_in[16];
    const float* w_ns       = (const float*)d_in[17];
    const float* w_rs       = (const float*)d_in[18];
    const float* fc1_w      = (const float*)d_in[19];
    const float* fc1_b      = (const float*)d_in[20];
    const float* fc2_w      = (const float*)d_in[21];
    const float* fc2_b      = (const float*)d_in[22];
    const int*   nidx       = (const int*)d_in[23];
    const int*   esrc       = (const int*)d_in[24];
    const int*   edst       = (const int*)d_in[25];
    const int*   ebatch     = (const int*)d_in[26];
    float* out = (float*)d_out;

    void *vp;
    cudaGetSymbolAddress(&vp, g_qw);     float* p_qw    = (float*)vp;
    cudaGetSymbolAddress(&vp, g_logits); float* p_logits= (float*)vp;
    cudaGetSymbolAddress(&vp, g_vocab);  float* p_vocab = (float*)vp;
    cudaGetSymbolAddress(&vp, g_tagged); float* p_tagged= (float*)vp;
    cudaGetSymbolAddress(&vp, g_xw);     float* p_xw    = (float*)vp;
    cudaGetSymbolAddress(&vp, g_WihT);   float* p_WihT  = (float*)vp;
    cudaGetSymbolAddress(&vp, g_WhhT);   float* p_WhhT  = (float*)vp;
    cudaGetSymbolAddress(&vp, g_rWihT);  float* p_rWihT = (float*)vp;
    cudaGetSymbolAddress(&vp, g_rWhhT);  float* p_rWhhT = (float*)vp;
    cudaGetSymbolAddress(&vp, g_fc1T);   float* p_fc1T  = (float*)vp;
    cudaGetSymbolAddress(&vp, g_fc2T);   float* p_fc2T  = (float*)vp;

    transpose_k<<<(H4*HH+255)/256, 256>>>(lstm_Wih, p_WihT, H4, HH);
    transpose_k<<<(H4*HH+255)/256, 256>>>(lstm_Whh, p_WhhT, H4, HH);
    transpose_k<<<(HH*HH+255)/256, 256>>>(rnn_Wih,  p_rWihT, HH, HH);
    transpose_k<<<(HH*HH+255)/256, 256>>>(rnn_Whh,  p_rWhhT, HH, HH);
    transpose_k<<<(600*600+255)/256, 256>>>(fc1_w, p_fc1T, 600, 600);
    transpose_k<<<(OUTD*600+255)/256, 256>>>(fc2_w, p_fc2T, OUTD, 600);
    copy_vocab_k<<<(CE*HH+255)/256, 256>>>(cvocab, demb);
    init_zero_k<<<(BB*HH+255)/256, 256>>>();
    count_k<<<(NND+255)/256, 256>>>(nidx);
    dist_init_k<<<(NND+255)/256, 256>>>(nidx);

    // tagging
    gemm_t<0><<<dim3((HH+63)/64, ML/64), 256>>>(questions, w_tag, p_qw, ML, HH, HH, HH, HH, HH);
    gemm_t<1><<<dim3((CE+63)/64, ML/64), 256>>>(p_qw, p_vocab, p_logits, ML, CE, HH, HH, HH, CE);
    softmax_rows_k<<<ML, 256>>>();
    gemm_t<0><<<dim3((HH+63)/64, ML/64), 256>>>(p_logits, cvocab, p_tagged, ML, HH, CCD, CE, HH, HH);
    tagged_adj_k<<<(ML*HH+255)/256, 256>>>(questions);

    // LSTM encoder
    gemm_t<0><<<dim3((H4+63)/64, ML/64), 256>>>(p_tagged, p_WihT, p_xw, ML, H4, HH, HH, H4, H4);
    for (int t = 0; t < LL; t++) lstm_step_k<<<BB, 600>>>(lstm_bih, lstm_bhh, t);

    // RNN decoder + attention
    rnn_ew_k<<<BB, HH>>>();
    for (int s = 0; s < 4; s++) rnn_step_k<<<BB, HH>>>(rnn_bih, rnn_bhh, s);
    attn_k<<<dim3(BB, 4), 128>>>();

    // message passing steps
    for (int s = 0; s < 3; s++) {
        psim_k<<<1, BB*9>>>(prop, s);
        vb_k<<<BB, 256>>>(s);
        zero_nl_k<<<(NND+255)/256, 256>>>();
        node_gemm_k<<<dim3(5, NND/128), 128>>>(node_attrs, nidx, Wp, w_ns);
        edge_gemm_k<<<dim3(5, EED/128), 128>>>(edge_attrs, ebatch, esrc, edst, We, w_rs, s);
        seg_softmax_k<<<BB, NPG>>>();
    }

    // final aggregation + head
    psim_k<<<1, BB*9>>>(prop, 3);
    agg_k<<<dim3(BB, 8), HH>>>(node_attrs);
    fc1_k<<<BB, 600>>>(fc1_b);
    fc2_k<<<dim3(BB, 8), 256>>>(fc2_b, out);
}

// round 5
// speedup vs baseline: 2.6666x; 2.6666x over previous
#include <cuda_runtime.h>
#include <cuda_bf16.h>
#include <math.h>

#define BB 64
#define LL 20
#define HH 300
#define PP 8
#define NND 32768
#define EED 262144
#define CCD 2048
#define CE 2049
#define OUTD 1845
#define H4 1200
#define K2 2400
#define NPG 512
#define ML (BB*LL)
#define NPAD 304
#define SPAD 24
#define BK 16

static __device__ float g_qw[ML*HH];
static __device__ float g_logits[ML*CE];
static __device__ float g_vocab[CE*HH];
static __device__ float g_tagged[ML*HH];
static __device__ float g_xw[ML*H4];
static __device__ float g_WihT[HH*H4];
static __device__ float g_WhhT[HH*H4];
static __device__ float g_rWihT[HH*HH];
static __device__ float g_rWhhT[HH*HH];
static __device__ float g_fc1T[600*600];
static __device__ float g_fc2T[600*OUTD];
static __device__ float g_h[BB*HH];
static __device__ float g_c[BB*HH];
static __device__ float g_hx[BB*HH];
static __device__ float g_ew[BB*HH];
static __device__ float g_hidden[BB*4*HH];
static __device__ float g_instr[BB*4*HH];
static __device__ float g_vb[BB*K2];
static __device__ float g_psim[BB*9];
static __device__ float g_dist[NND];
static __device__ float g_nsl[NND];
static __device__ float g_nrl[NND];
static __device__ float g_agg[BB*HH];
static __device__ float g_feat1[BB*600];
static __device__ float g_cnt[BB];

__device__ __forceinline__ float sigf(float x){ return 1.f/(1.f+expf(-x)); }
__device__ __forceinline__ float eluf(float x){ return x > 0.f ? x : expm1f(x); }

__device__ __forceinline__ void mma16816(float* d, const unsigned* a, const unsigned* b) {
    asm volatile(
        "mma.sync.aligned.m16n8k16.row.col.f32.bf16.bf16.f32 "
        "{%0,%1,%2,%3}, {%4,%5,%6,%7}, {%8,%9}, {%0,%1,%2,%3};\n"
        : "+f"(d[0]), "+f"(d[1]), "+f"(d[2]), "+f"(d[3])
        : "r"(a[0]), "r"(a[1]), "r"(a[2]), "r"(a[3]), "r"(b[0]), "r"(b[1]));
}

__global__ void transpose_k(const float* __restrict__ src, float* __restrict__ dst, int R, int C) {
    int idx = blockIdx.x*blockDim.x + threadIdx.x;
    if (idx < R*C) { int r = idx / C, c = idx % C; dst[c*R + r] = src[idx]; }
}

__global__ void copy_vocab_k(const float* __restrict__ cv, const float* __restrict__ demb) {
    int idx = blockIdx.x*blockDim.x + threadIdx.x;
    if (idx < CE*HH) { int c = idx / HH, h = idx % HH; g_vocab[idx] = (c < CCD) ? cv[idx] : demb[h]; }
}

__global__ void init_zero_k() {
    int idx = blockIdx.x*blockDim.x + threadIdx.x;
    if (idx < BB*HH) { g_h[idx]=0.f; g_c[idx]=0.f; g_hx[idx]=0.f; g_agg[idx]=0.f; }
    if (idx < BB) g_cnt[idx]=0.f;
}

__global__ void count_k(const int* __restrict__ nidx) {
    int n = blockIdx.x*blockDim.x + threadIdx.x;
    if (n < NND) atomicAdd(&g_cnt[nidx[n]], 1.f);
}

__global__ void dist_init_k(const int* __restrict__ nidx) {
    int n = blockIdx.x*blockDim.x + threadIdx.x;
    if (n < NND) g_dist[n] = 1.f / g_cnt[nidx[n]];
}

__global__ void zero_nl_k() {
    int n = blockIdx.x*blockDim.x + threadIdx.x;
    if (n < NND) { g_nsl[n]=0.f; g_nrl[n]=0.f; }
}

// generic 64x64 tiled GEMM, 4x4 micro-tile. TB=1 -> C = A @ B^T (B is Nc x K)
template<int TB>
__global__ void gemm_t(const float* __restrict__ A, const float* __restrict__ Bm,
                       float* __restrict__ C, int M, int Nc, int K,
                       int lda, int ldb, int ldc) {
    __shared__ float As[64][17];
    __shared__ float Bs[16][65];
    int tid = threadIdx.x;
    int tx = tid & 15, ty = tid >> 4;
    int row0 = blockIdx.y * 64, c0 = blockIdx.x * 64;
    float acc[4][4];
    #pragma unroll
    for (int i=0;i<4;i++) for (int j=0;j<4;j++) acc[i][j]=0.f;
    for (int k0 = 0; k0 < K; k0 += 16) {
        #pragma unroll
        for (int i = 0; i < 4; i++) {
            int e = tid + 256*i;
            int r = e >> 4, kk = e & 15;
            As[r][kk] = (k0+kk < K) ? A[(row0+r)*lda + k0+kk] : 0.f;
            if (TB) {
                int cc = e >> 4, kb = e & 15;
                Bs[kb][cc] = (k0+kb < K && c0+cc < Nc) ? Bm[(c0+cc)*ldb + k0+kb] : 0.f;
            } else {
                int cc = e & 63, kb = e >> 6;
                Bs[kb][cc] = (k0+kb < K && c0+cc < Nc) ? Bm[(k0+kb)*ldb + c0+cc] : 0.f;
            }
        }
        __syncthreads();
        #pragma unroll
        for (int kk = 0; kk < 16; kk++) {
            float ra[4], rb[4];
            #pragma unroll
            for (int i=0;i<4;i++) ra[i] = As[ty*4+i][kk];
            #pragma unroll
            for (int j=0;j<4;j++) rb[j] = Bs[kk][tx*4+j];
            #pragma unroll
            for (int i=0;i<4;i++) for (int j=0;j<4;j++) acc[i][j] += ra[i]*rb[j];
        }
        __syncthreads();
    }
    #pragma unroll
    for (int i=0;i<4;i++)
        #pragma unroll
        for (int j=0;j<4;j++) {
            int c = c0 + tx*4 + j;
            if (c < Nc) C[(row0+ty*4+i)*ldc + c] = acc[i][j];
        }
}

__global__ void softmax_rows_k() {
    __shared__ float red[256];
    int m = blockIdx.x, t = threadIdx.x;
    float* p = &g_logits[m*CE];
    float v = -1e30f;
    for (int i = t; i < CE; i += 256) v = fmaxf(v, p[i]);
    red[t] = v; __syncthreads();
    for (int s = 128; s > 0; s >>= 1) { if (t < s) red[t] = fmaxf(red[t], red[t+s]); __syncthreads(); }
    float mx = red[0]; __syncthreads();
    float sum = 0.f;
    for (int i = t; i < CE; i += 256) { float e = expf(p[i]-mx); p[i] = e; sum += e; }
    red[t] = sum; __syncthreads();
    for (int s = 128; s > 0; s >>= 1) { if (t < s) red[t] += red[t+s]; __syncthreads(); }
    float inv = 1.f / red[0];
    for (int i = t; i < CE; i += 256) p[i] *= inv;
}

__global__ void tagged_adj_k(const float* __restrict__ questions) {
    int idx = blockIdx.x*blockDim.x + threadIdx.x;
    if (idx < ML*HH) g_tagged[idx] += g_logits[(idx/HH)*CE + CCD] * questions[idx];
}

__global__ void lstm_step_k(const float* __restrict__ bih, const float* __restrict__ bhh, int t) {
    int b = blockIdx.x, tid = threadIdx.x;   // 600 threads
    __shared__ float hs[HH];
    __shared__ float z[H4];
    if (tid < HH) hs[tid] = g_h[b*HH + tid];
    __syncthreads();
    for (int j = tid; j < H4; j += 600) {
        float a = g_xw[(b*LL + t)*H4 + j] + bih[j] + bhh[j];
        #pragma unroll 4
        for (int h = 0; h < HH; h++) a += g_WhhT[h*H4 + j] * hs[h];
        z[j] = a;
    }
    __syncthreads();
    if (tid < HH) {
        float iv = sigf(z[tid]), fv = sigf(z[HH+tid]);
        float gv = tanhf(z[2*HH+tid]), ov = sigf(z[3*HH+tid]);
        float c = fv * g_c[b*HH+tid] + iv*gv;
        g_c[b*HH+tid] = c;
        g_h[b*HH+tid] = ov * tanhf(c);
    }
}

__global__ void rnn_ew_k() {
    int b = blockIdx.x, k = threadIdx.x;     // 300 threads
    __shared__ float es[HH];
    es[k] = g_h[b*HH + k];
    __syncthreads();
    float a = 0.f;
    #pragma unroll 4
    for (int h = 0; h < HH; h++) a += g_rWihT[h*HH + k] * es[h];
    g_ew[b*HH + k] = a;
}

__global__ void rnn_step_k(const float* __restrict__ rbih, const float* __restrict__ rbhh, int s) {
    int b = blockIdx.x, k = threadIdx.x;
    __shared__ float hs[HH];
    hs[k] = g_hx[b*HH + k];
    __syncthreads();
    float a = g_ew[b*HH + k] + rbih[k] + rbhh[k];
    #pragma unroll 4
    for (int h = 0; h < HH; h++) a += g_rWhhT[h*HH + k] * hs[h];
    a = fmaxf(a, 0.f);
    g_hx[b*HH + k] = a;
    g_hidden[(b*4 + s)*HH + k] = a;
}

__global__ void attn_k() {
    int b = blockIdx.x, ii = blockIdx.y, tid = threadIdx.x;   // 128 threads
    __shared__ float hid[HH];
    __shared__ float sc[LL];
    for (int k = tid; k < HH; k += 128) hid[k] = g_hidden[(b*4+ii)*HH + k];
    __syncthreads();
    int warp = tid >> 5, lane = tid & 31;
    for (int l = warp; l < LL; l += 4) {
        float a = 0.f;
        for (int h = lane; h < HH; h += 32) a += hid[h] * g_tagged[(b*LL+l)*HH + h];
        #pragma unroll
        for (int o = 16; o > 0; o >>= 1) a += __shfl_xor_sync(0xffffffffu, a, o);
        if (lane == 0) sc[l] = a;
    }
    __syncthreads();
    if (tid == 0) {
        float mx = -1e30f;
        for (int l = 0; l < LL; l++) mx = fmaxf(mx, sc[l]);
        float sum = 0.f;
        for (int l = 0; l < LL; l++) { sc[l] = expf(sc[l]-mx); sum += sc[l]; }
        for (int l = 0; l < LL; l++) sc[l] /= sum;
    }
    __syncthreads();
    for (int k = tid; k < HH; k += 128) {
        float a = 0.f;
        #pragma unroll
        for (int l = 0; l < LL; l++) a += sc[l] * g_tagged[(b*LL+l)*HH + k];
        g_instr[(b*4+ii)*HH + k] = a;
    }
}

__global__ void psim_k(const float* __restrict__ prop, int step) {
    __shared__ float s[BB*9];
    int tid = threadIdx.x;                  // 576 threads, 1 block
    int b = tid / 9, p = tid % 9;
    const float* ins = &g_instr[(b*4+step)*HH];
    float a = 0.f;
    for (int h = 0; h < HH; h++) a += ins[h] * prop[p*HH + h];
    s[tid] = a;
    __syncthreads();
    if (p == 0) {
        float mx = -1e30f;
        for (int q = 0; q < 9; q++) mx = fmaxf(mx, s[b*9+q]);
        float e[9], sum = 0.f;
        for (int q = 0; q < 9; q++) { e[q] = expf(s[b*9+q]-mx); sum += e[q]; }
        for (int q = 0; q < 9; q++) g_psim[b*9+q] = e[q]/sum;
    }
}

__global__ void vb_k(int step) {
    int b = blockIdx.x;
    for (int j = threadIdx.x; j < K2; j += 256)
        g_vb[b*K2 + j] = g_psim[b*9 + j/HH] * g_instr[(b*4+step)*HH + j%HH];
}

// ------------- tensor-core GEMM (split-bf16 x3), fused epilogue -------------
// IS_EDGE=0: A[n,j]=attrs[n,j]*vb[b(n),j], K=2400, epilogue -> g_nsl[n]
// IS_EDGE=1: A[e,j]=eattrs[e,j]*instr[b(e),j], K=300(pad 304),
//            epilogue -> g_nrl[edst[e]] += dist[esrc[e]]*part
template<int IS_EDGE>
__global__ __launch_bounds__(512, 1)
void mma_gemm_k(const float* __restrict__ Asrc, const int* __restrict__ rowb,
                const int* __restrict__ esrc, const int* __restrict__ edst,
                const float* __restrict__ Bsrc, const float* __restrict__ wv,
                int step) {
    __shared__ __align__(16) __nv_bfloat16 As_h[128][SPAD];
    __shared__ __align__(16) __nv_bfloat16 As_l[128][SPAD];
    __shared__ __align__(16) __nv_bfloat16 Bs_h[NPAD][SPAD];
    __shared__ __align__(16) __nv_bfloat16 Bs_l[NPAD][SPAD];
    __shared__ int rb[128];
    const int KT = IS_EDGE ? 19 : 150;
    int tid = threadIdx.x;
    int row0 = blockIdx.x * 128;
    if (tid < 128) rb[tid] = rowb[row0 + tid];
    __syncthreads();
    int warp = tid >> 5, lane = tid & 31;
    int wm = warp & 7, wn = warp >> 3;
    int g = lane >> 2, q = lane & 3;
    int k0 = q * 2;
    float acc[19][4];
    #pragma unroll
    for (int t = 0; t < 19; t++) { acc[t][0]=0.f; acc[t][1]=0.f; acc[t][2]=0.f; acc[t][3]=0.f; }

    for (int kt = 0; kt < KT; kt++) {
        int j0 = kt * BK;
        // fill A tile (128 x 16), split hi/lo
        #pragma unroll
        for (int i = 0; i < 4; i++) {
            int e = tid + 512*i;
            int r = e >> 4, kk = e & 15;
            int j = j0 + kk;
            float v;
            if (!IS_EDGE) {
                v = Asrc[(row0 + r)*K2 + j] * g_vb[rb[r]*K2 + j];
            } else {
                v = (j < HH) ? Asrc[(row0 + r)*HH + j] * g_instr[(rb[r]*4 + step)*HH + j] : 0.f;
            }
            __nv_bfloat16 h = __float2bfloat16(v);
            As_h[r][kk] = h;
            As_l[r][kk] = __float2bfloat16(v - __bfloat162float(h));
        }
        // fill B tile (304 x 16) from row-major B[j,c], split hi/lo
        #pragma unroll
        for (int i = 0; i < 10; i++) {
            int e = tid + 512*i;
            if (e < NPAD*BK) {
                int kk = e / NPAD, n = e - kk*NPAD;
                int j = j0 + kk;
                float v = (n < HH && (!IS_EDGE || j < HH)) ? Bsrc[j*HH + n] : 0.f;
                __nv_bfloat16 h = __float2bfloat16(v);
                Bs_h[n][kk] = h;
                Bs_l[n][kk] = __float2bfloat16(v - __bfloat162float(h));
            }
        }
        __syncthreads();
        // A fragments
        int r = wm*16 + g;
        unsigned ah[4], al[4];
        ah[0] = *(const unsigned*)&As_h[r  ][k0];
        ah[1] = *(const unsigned*)&As_h[r+8][k0];
        ah[2] = *(const unsigned*)&As_h[r  ][k0+8];
        ah[3] = *(const unsigned*)&As_h[r+8][k0+8];
        al[0] = *(const unsigned*)&As_l[r  ][k0];
        al[1] = *(const unsigned*)&As_l[r+8][k0];
        al[2] = *(const unsigned*)&As_l[r  ][k0+8];
        al[3] = *(const unsigned*)&As_l[r+8][k0+8];
        #pragma unroll
        for (int t = 0; t < 19; t++) {
            int n = wn*152 + t*8 + g;
            unsigned bh[2], bl[2];
            bh[0] = *(const unsigned*)&Bs_h[n][k0];
            bh[1] = *(const unsigned*)&Bs_h[n][k0+8];
            bl[0] = *(const unsigned*)&Bs_l[n][k0];
            bl[1] = *(const unsigned*)&Bs_l[n][k0+8];
            mma16816(acc[t], ah, bh);
            mma16816(acc[t], ah, bl);
            mma16816(acc[t], al, bh);
        }
        __syncthreads();
    }
    // epilogue: elu, dot with wv over columns, reduce over quad, atomic per row
    float pa = 0.f, pb = 0.f;
    #pragma unroll
    for (int t = 0; t < 19; t++) {
        int c0 = wn*152 + t*8 + q*2;
        #pragma unroll
        for (int jj = 0; jj < 2; jj++) {
            int c = c0 + jj;
            if (c < HH) {
                float w = wv[c];
                float v0 = acc[t][jj];     v0 = v0 > 0.f ? v0 : expm1f(v0);
                float v1 = acc[t][2+jj];   v1 = v1 > 0.f ? v1 : expm1f(v1);
                pa += v0 * w;
                pb += v1 * w;
            }
        }
    }
    pa += __shfl_xor_sync(0xffffffffu, pa, 1);
    pa += __shfl_xor_sync(0xffffffffu, pa, 2);
    pb += __shfl_xor_sync(0xffffffffu, pb, 1);
    pb += __shfl_xor_sync(0xffffffffu, pb, 2);
    if (q == 0) {
        int rA = row0 + wm*16 + g;
        int rB = rA + 8;
        if (!IS_EDGE) {
            atomicAdd(&g_nsl[rA], pa);
            atomicAdd(&g_nsl[rB], pb);
        } else {
            atomicAdd(&g_nrl[edst[rA]], g_dist[esrc[rA]] * pa);
            atomicAdd(&g_nrl[edst[rB]], g_dist[esrc[rB]] * pb);
        }
    }
}

__global__ void seg_softmax_k() {
    __shared__ float red[NPG];
    int b = blockIdx.x, t = threadIdx.x;   // 512 threads
    int n = b*NPG + t;
    float v1 = g_nsl[n], v2 = g_nrl[n];
    red[t] = v1; __syncthreads();
    for (int s = 256; s > 0; s >>= 1) { if (t < s) red[t] = fmaxf(red[t], red[t+s]); __syncthreads(); }
    float m1 = red[0]; __syncthreads();
    float e1 = expf(v1 - m1);
    red[t] = e1; __syncthreads();
    for (int s = 256; s > 0; s >>= 1) { if (t < s) red[t] += red[t+s]; __syncthreads(); }
    float s1 = red[0]; __syncthreads();
    red[t] = v2; __syncthreads();
    for (int s = 256; s > 0; s >>= 1) { if (t < s) red[t] = fmaxf(red[t], red[t+s]); __syncthreads(); }
    float m2 = red[0]; __syncthreads();
    float e2 = expf(v2 - m2);
    red[t] = e2; __syncthreads();
    for (int s = 256; s > 0; s >>= 1) { if (t < s) red[t] += red[t+s]; __syncthreads(); }
    float s2 = red[0]; __syncthreads();
    float rs = g_psim[b*9 + 8];
    g_dist[n] = rs * (e2/s2) + (1.f - rs) * (e1/s1);
}

__global__ void agg_k(const float* __restrict__ attrs) {
    int b = blockIdx.x, ch = blockIdx.y, h = threadIdx.x;  // 300 threads, y=8 chunks
    __shared__ float np[8];
    if (h < 8) np[h] = g_psim[b*9 + h];
    __syncthreads();
    float acc = 0.f;
    int nbase = b*NPG + ch*(NPG/8);
    for (int nn = 0; nn < NPG/8; nn++) {
        int n = nbase + nn;
        float d = g_dist[n], w = 0.f;
        #pragma unroll
        for (int p = 0; p < 8; p++) w += np[p] * attrs[(n*PP + p)*HH + h];
        acc += d * w;
    }
    atomicAdd(&g_agg[b*HH + h], acc);
}

__global__ void fc1_k(const float* __restrict__ fc1b) {
    int b = blockIdx.x, j = threadIdx.x;   // 600 threads
    __shared__ float fs[600];
    fs[j] = (j < HH) ? g_h[b*HH + j] : g_agg[b*HH + (j - HH)];
    __syncthreads();
    float a = fc1b[j];
    #pragma unroll 4
    for (int k = 0; k < 600; k++) a += g_fc1T[k*600 + j] * fs[k];
    g_feat1[b*600 + j] = eluf(a);
}

__global__ void fc2_k(const float* __restrict__ fc2b, float* __restrict__ out) {
    int b = blockIdx.x, t = threadIdx.x;   // 256 threads, y=8
    __shared__ float f1[600];
    for (int k = t; k < 600; k += 256) f1[k] = g_feat1[b*600 + k];
    __syncthreads();
    int o = blockIdx.y*256 + t;
    if (o < OUTD) {
        float a = fc2b[o];
        #pragma unroll 4
        for (int k = 0; k < 600; k++) a += g_fc2T[k*OUTD + o] * f1[k];
        out[b*OUTD + o] = a;
    }
}

extern "C" void kernel_launch(void* const* d_in, const int* in_sizes, int n_in,
                              void* d_out, int out_size) {
    (void)in_sizes; (void)n_in; (void)out_size;
    const float* questions  = (const float*)d_in[0];
    const float* cvocab     = (const float*)d_in[1];
    const float* prop       = (const float*)d_in[2];
    const float* node_attrs = (const float*)d_in[3];
    const float* edge_attrs = (const float*)d_in[4];
    const float* w_tag      = (const float*)d_in[5];
    const float* demb       = (const float*)d_in[6];
    const float* lstm_Wih   = (const float*)d_in[7];
    const float* lstm_Whh   = (const float*)d_in[8];
    const float* lstm_bih   = (const float*)d_in[9];
    const float* lstm_bhh   = (const float*)d_in[10];
    const float* rnn_Wih    = (const float*)d_in[11];
    const float* rnn_Whh    = (const float*)d_in[12];
    const float* rnn_bih    = (const float*)d_in[13];
    const float* rnn_bhh    = (const float*)d_in[14];
    const float* Wp         = (const float*)d_in[15];
    const float* We         = (const float*)d_in[16];
    const float* w_ns       = (const float*)d_in[17];
    const float* w_rs       = (const float*)d_in[18];
    const float* fc1_w      = (const float*)d_in[19];
    const float* fc1_b      = (const float*)d_in[20];
    const float* fc2_w      = (const float*)d_in[21];
    const float* fc2_b      = (const float*)d_in[22];
    const int*   nidx       = (const int*)d_in[23];
    const int*   esrc       = (const int*)d_in[24];
    const int*   edst       = (const int*)d_in[25];
    const int*   ebatch     = (const int*)d_in[26];
    float* out = (float*)d_out;

    void *vp;
    cudaGetSymbolAddress(&vp, g_qw);     float* p_qw    = (float*)vp;
    cudaGetSymbolAddress(&vp, g_logits); float* p_logits= (float*)vp;
    cudaGetSymbolAddress(&vp, g_vocab);  float* p_vocab = (float*)vp;
    cudaGetSymbolAddress(&vp, g_tagged); float* p_tagged= (float*)vp;
    cudaGetSymbolAddress(&vp, g_xw);     float* p_xw    = (float*)vp;
    cudaGetSymbolAddress(&vp, g_WihT);   float* p_WihT  = (float*)vp;
    cudaGetSymbolAddress(&vp, g_WhhT);   float* p_WhhT  = (float*)vp;
    cudaGetSymbolAddress(&vp, g_rWihT);  float* p_rWihT = (float*)vp;
    cudaGetSymbolAddress(&vp, g_rWhhT);  float* p_rWhhT = (float*)vp;
    cudaGetSymbolAddress(&vp, g_fc1T);   float* p_fc1T  = (float*)vp;
    cudaGetSymbolAddress(&vp, g_fc2T);   float* p_fc2T  = (float*)vp;

    transpose_k<<<(H4*HH+255)/256, 256>>>(lstm_Wih, p_WihT, H4, HH);
    transpose_k<<<(H4*HH+255)/256, 256>>>(lstm_Whh, p_WhhT, H4, HH);
    transpose_k<<<(HH*HH+255)/256, 256>>>(rnn_Wih,  p_rWihT, HH, HH);
    transpose_k<<<(HH*HH+255)/256, 256>>>(rnn_Whh,  p_rWhhT, HH, HH);
    transpose_k<<<(600*600+255)/256, 256>>>(fc1_w, p_fc1T, 600, 600);
    transpose_k<<<(OUTD*600+255)/256, 256>>>(fc2_w, p_fc2T, OUTD, 600);
    copy_vocab_k<<<(CE*HH+255)/256, 256>>>(cvocab, demb);
    init_zero_k<<<(BB*HH+255)/256, 256>>>();
    count_k<<<(NND+255)/256, 256>>>(nidx);
    dist_init_k<<<(NND+255)/256, 256>>>(nidx);

    // tagging
    gemm_t<0><<<dim3((HH+63)/64, ML/64), 256>>>(questions, w_tag, p_qw, ML, HH, HH, HH, HH, HH);
    gemm_t<1><<<dim3((CE+63)/64, ML/64), 256>>>(p_qw, p_vocab, p_logits, ML, CE, HH, HH, HH, CE);
    softmax_rows_k<<<ML, 256>>>();
    gemm_t<0><<<dim3((HH+63)/64, ML/64), 256>>>(p_logits, cvocab, p_tagged, ML, HH, CCD, CE, HH, HH);
    tagged_adj_k<<<(ML*HH+255)/256, 256>>>(questions);

    // LSTM encoder
    gemm_t<0><<<dim3((H4+63)/64, ML/64), 256>>>(p_tagged, p_WihT, p_xw, ML, H4, HH, HH, H4, H4);
    for (int t = 0; t < LL; t++) lstm_step_k<<<BB, 600>>>(lstm_bih, lstm_bhh, t);

    // RNN decoder + attention
    rnn_ew_k<<<BB, HH>>>();
    for (int s = 0; s < 4; s++) rnn_step_k<<<BB, HH>>>(rnn_bih, rnn_bhh, s);
    attn_k<<<dim3(BB, 4), 128>>>();

    // message passing steps (tensor-core GEMMs)
    for (int s = 0; s < 3; s++) {
        psim_k<<<1, BB*9>>>(prop, s);
        vb_k<<<BB, 256>>>(s);
        zero_nl_k<<<(NND+255)/256, 256>>>();
        mma_gemm_k<0><<<NND/128, 512>>>(node_attrs, nidx, esrc, edst, Wp, w_ns, s);
        mma_gemm_k<1><<<EED/128, 512>>>(edge_attrs, ebatch, esrc, edst, We, w_rs, s);
        seg_softmax_k<<<BB, NPG>>>();
    }

    // final aggregation + head
    psim_k<<<1, BB*9>>>(prop, 3);
    agg_k<<<dim3(BB, 8), HH>>>(node_attrs);
    fc1_k<<<BB, 600>>>(fc1_b);
    fc2_k<<<dim3(BB, 8), 256>>>(fc2_b, out);
}

// round 9
// speedup vs baseline: 4.6989x; 1.7621x over previous
#include <cuda_runtime.h>
#include <cuda_bf16.h>
#include <math.h>

#define BB 64
#define LL 20
#define HH 300
#define PP 8
#define NND 32768
#define EED 262144
#define CCD 2048
#define CE 2049
#define OUTD 1845
#define H4 1200
#define K2 2400
#define NPG 512
#define ML (BB*LL)
#define NPAD 304
#define SPAD 24
#define BK 16
#define SMEM_MMA 92544

static __device__ float g_qw[ML*HH];
static __device__ float g_logits[ML*CE];
static __device__ float g_vocab[CE*HH];
static __device__ float g_tagged[ML*HH];
static __device__ float g_xw[ML*H4];
static __device__ float g_WihT[HH*H4];
static __device__ float g_WhhT[HH*H4];
static __device__ float g_rWihT[HH*HH];
static __device__ float g_rWhhT[HH*HH];
static __device__ float g_fc1T[600*600];
static __device__ float g_fc2T[600*OUTD];
static __device__ float g_h[BB*HH];
static __device__ float g_c[BB*HH];
static __device__ float g_hx[BB*HH];
static __device__ float g_ew[BB*HH];
static __device__ float g_hidden[BB*4*HH];
static __device__ float g_instr[BB*4*HH];
static __device__ float g_vb[BB*K2];
static __device__ float g_psim[BB*9];
static __device__ float g_dist[NND];
static __device__ float g_nsl[NND];
static __device__ float g_nrl[NND];
static __device__ float g_agg[BB*HH];
static __device__ float g_feat1[BB*600];
static __device__ float g_cnt[BB];
// precomputed split-bf16 weight planes, k-major [j][n]
static __device__ __align__(16) __nv_bfloat16 g_wph[K2*NPAD];
static __device__ __align__(16) __nv_bfloat16 g_wpl[K2*NPAD];
static __device__ __align__(16) __nv_bfloat16 g_weh[NPAD*NPAD];
static __device__ __align__(16) __nv_bfloat16 g_wel[NPAD*NPAD];

__device__ __forceinline__ float sigf(float x){ return 1.f/(1.f+expf(-x)); }
__device__ __forceinline__ float eluf(float x){ return x > 0.f ? x : expm1f(x); }

__device__ __forceinline__ void mma16816(float* d, const unsigned* a, const unsigned* b) {
    asm volatile(
        "mma.sync.aligned.m16n8k16.row.col.f32.bf16.bf16.f32 "
        "{%0,%1,%2,%3}, {%4,%5,%6,%7}, {%8,%9}, {%0,%1,%2,%3};\n"
        : "+f"(d[0]), "+f"(d[1]), "+f"(d[2]), "+f"(d[3])
        : "r"(a[0]), "r"(a[1]), "r"(a[2]), "r"(a[3]), "r"(b[0]), "r"(b[1]));
}

__global__ void transpose_k(const float* __restrict__ src, float* __restrict__ dst, int R, int C) {
    int idx = blockIdx.x*blockDim.x + threadIdx.x;
    if (idx < R*C) { int r = idx / C, c = idx % C; dst[c*R + r] = src[idx]; }
}

__global__ void copy_vocab_k(const float* __restrict__ cv, const float* __restrict__ demb) {
    int idx = blockIdx.x*blockDim.x + threadIdx.x;
    if (idx < CE*HH) { int c = idx / HH, h = idx % HH; g_vocab[idx] = (c < CCD) ? cv[idx] : demb[h]; }
}

__global__ void init_zero_k() {
    int idx = blockIdx.x*blockDim.x + threadIdx.x;
    if (idx < BB*HH) { g_h[idx]=0.f; g_c[idx]=0.f; g_hx[idx]=0.f; g_agg[idx]=0.f; }
    if (idx < BB) g_cnt[idx]=0.f;
}

__global__ void count_k(const int* __restrict__ nidx) {
    int n = blockIdx.x*blockDim.x + threadIdx.x;
    if (n < NND) atomicAdd(&g_cnt[nidx[n]], 1.f);
}

__global__ void dist_init_k(const int* __restrict__ nidx) {
    int n = blockIdx.x*blockDim.x + threadIdx.x;
    if (n < NND) g_dist[n] = 1.f / g_cnt[nidx[n]];
}

__global__ void zero_nl_k() {
    int n = blockIdx.x*blockDim.x + threadIdx.x;
    if (n < NND) { g_nsl[n]=0.f; g_nrl[n]=0.f; }
}

__global__ void split_wp_k(const float* __restrict__ Wp) {
    int idx = blockIdx.x*blockDim.x + threadIdx.x;
    if (idx < K2*NPAD) {
        int j = idx / NPAD, n = idx % NPAD;
        float v = (n < HH) ? Wp[j*HH + n] : 0.f;
        __nv_bfloat16 h = __float2bfloat16(v);
        g_wph[idx] = h;
        g_wpl[idx] = __float2bfloat16(v - __bfloat162float(h));
    }
}

__global__ void split_we_k(const float* __restrict__ We) {
    int idx = blockIdx.x*blockDim.x + threadIdx.x;
    if (idx < NPAD*NPAD) {
        int j = idx / NPAD, n = idx % NPAD;
        float v = (j < HH && n < HH) ? We[j*HH + n] : 0.f;
        __nv_bfloat16 h = __float2bfloat16(v);
        g_weh[idx] = h;
        g_wel[idx] = __float2bfloat16(v - __bfloat162float(h));
    }
}

// generic 64x64 tiled GEMM, 4x4 micro-tile. TB=1 -> C = A @ B^T (B is Nc x K)
template<int TB>
__global__ void gemm_t(const float* __restrict__ A, const float* __restrict__ Bm,
                       float* __restrict__ C, int M, int Nc, int K,
                       int lda, int ldb, int ldc) {
    __shared__ float As[64][17];
    __shared__ float Bs[16][65];
    int tid = threadIdx.x;
    int tx = tid & 15, ty = tid >> 4;
    int row0 = blockIdx.y * 64, c0 = blockIdx.x * 64;
    float acc[4][4];
    #pragma unroll
    for (int i=0;i<4;i++) for (int j=0;j<4;j++) acc[i][j]=0.f;
    for (int k0 = 0; k0 < K; k0 += 16) {
        #pragma unroll
        for (int i = 0; i < 4; i++) {
            int e = tid + 256*i;
            int r = e >> 4, kk = e & 15;
            As[r][kk] = (k0+kk < K) ? A[(row0+r)*lda + k0+kk] : 0.f;
            if (TB) {
                int cc = e >> 4, kb = e & 15;
                Bs[kb][cc] = (k0+kb < K && c0+cc < Nc) ? Bm[(c0+cc)*ldb + k0+kb] : 0.f;
            } else {
                int cc = e & 63, kb = e >> 6;
                Bs[kb][cc] = (k0+kb < K && c0+cc < Nc) ? Bm[(k0+kb)*ldb + c0+cc] : 0.f;
            }
        }
        __syncthreads();
        #pragma unroll
        for (int kk = 0; kk < 16; kk++) {
            float ra[4], rb[4];
            #pragma unroll
            for (int i=0;i<4;i++) ra[i] = As[ty*4+i][kk];
            #pragma unroll
            for (int j=0;j<4;j++) rb[j] = Bs[kk][tx*4+j];
            #pragma unroll
            for (int i=0;i<4;i++) for (int j=0;j<4;j++) acc[i][j] += ra[i]*rb[j];
        }
        __syncthreads();
    }
    #pragma unroll
    for (int i=0;i<4;i++)
        #pragma unroll
        for (int j=0;j<4;j++) {
            int c = c0 + tx*4 + j;
            if (c < Nc) C[(row0+ty*4+i)*ldc + c] = acc[i][j];
        }
}

__global__ void softmax_rows_k() {
    __shared__ float red[256];
    int m = blockIdx.x, t = threadIdx.x;
    float* p = &g_logits[m*CE];
    float v = -1e30f;
    for (int i = t; i < CE; i += 256) v = fmaxf(v, p[i]);
    red[t] = v; __syncthreads();
    for (int s = 128; s > 0; s >>= 1) { if (t < s) red[t] = fmaxf(red[t], red[t+s]); __syncthreads(); }
    float mx = red[0]; __syncthreads();
    float sum = 0.f;
    for (int i = t; i < CE; i += 256) { float e = expf(p[i]-mx); p[i] = e; sum += e; }
    red[t] = sum; __syncthreads();
    for (int s = 128; s > 0; s >>= 1) { if (t < s) red[t] += red[t+s]; __syncthreads(); }
    float inv = 1.f / red[0];
    for (int i = t; i < CE; i += 256) p[i] *= inv;
}

__global__ void tagged_adj_k(const float* __restrict__ questions) {
    int idx = blockIdx.x*blockDim.x + threadIdx.x;
    if (idx < ML*HH) g_tagged[idx] += g_logits[(idx/HH)*CE + CCD] * questions[idx];
}

__global__ void lstm_step_k(const float* __restrict__ bih, const float* __restrict__ bhh, int t) {
    int b = blockIdx.x, tid = threadIdx.x;   // 600 threads
    __shared__ float hs[HH];
    __shared__ float z[H4];
    if (tid < HH) hs[tid] = g_h[b*HH + tid];
    __syncthreads();
    for (int j = tid; j < H4; j += 600) {
        float a = g_xw[(b*LL + t)*H4 + j] + bih[j] + bhh[j];
        #pragma unroll 4
        for (int h = 0; h < HH; h++) a += g_WhhT[h*H4 + j] * hs[h];
        z[j] = a;
    }
    __syncthreads();
    if (tid < HH) {
        float iv = sigf(z[tid]), fv = sigf(z[HH+tid]);
        float gv = tanhf(z[2*HH+tid]), ov = sigf(z[3*HH+tid]);
        float c = fv * g_c[b*HH+tid] + iv*gv;
        g_c[b*HH+tid] = c;
        g_h[b*HH+tid] = ov * tanhf(c);
    }
}

__global__ void rnn_ew_k() {
    int b = blockIdx.x, k = threadIdx.x;     // 300 threads
    __shared__ float es[HH];
    es[k] = g_h[b*HH + k];
    __syncthreads();
    float a = 0.f;
    #pragma unroll 4
    for (int h = 0; h < HH; h++) a += g_rWihT[h*HH + k] * es[h];
    g_ew[b*HH + k] = a;
}

__global__ void rnn_step_k(const float* __restrict__ rbih, const float* __restrict__ rbhh, int s) {
    int b = blockIdx.x, k = threadIdx.x;
    __shared__ float hs[HH];
    hs[k] = g_hx[b*HH + k];
    __syncthreads();
    float a = g_ew[b*HH + k] + rbih[k] + rbhh[k];
    #pragma unroll 4
    for (int h = 0; h < HH; h++) a += g_rWhhT[h*HH + k] * hs[h];
    a = fmaxf(a, 0.f);
    g_hx[b*HH + k] = a;
    g_hidden[(b*4 + s)*HH + k] = a;
}

__global__ void attn_k() {
    int b = blockIdx.x, ii = blockIdx.y, tid = threadIdx.x;   // 128 threads
    __shared__ float hid[HH];
    __shared__ float sc[LL];
    for (int k = tid; k < HH; k += 128) hid[k] = g_hidden[(b*4+ii)*HH + k];
    __syncthreads();
    int warp = tid >> 5, lane = tid & 31;
    for (int l = warp; l < LL; l += 4) {
        float a = 0.f;
        for (int h = lane; h < HH; h += 32) a += hid[h] * g_tagged[(b*LL+l)*HH + h];
        #pragma unroll
        for (int o = 16; o > 0; o >>= 1) a += __shfl_xor_sync(0xffffffffu, a, o);
        if (lane == 0) sc[l] = a;
    }
    __syncthreads();
    if (tid == 0) {
        float mx = -1e30f;
        for (int l = 0; l < LL; l++) mx = fmaxf(mx, sc[l]);
        float sum = 0.f;
        for (int l = 0; l < LL; l++) { sc[l] = expf(sc[l]-mx); sum += sc[l]; }
        for (int l = 0; l < LL; l++) sc[l] /= sum;
    }
    __syncthreads();
    for (int k = tid; k < HH; k += 128) {
        float a = 0.f;
        #pragma unroll
        for (int l = 0; l < LL; l++) a += sc[l] * g_tagged[(b*LL+l)*HH + k];
        g_instr[(b*4+ii)*HH + k] = a;
    }
}

__global__ void psim_k(const float* __restrict__ prop, int step) {
    __shared__ float s[BB*9];
    int tid = threadIdx.x;                  // 576 threads, 1 block
    int b = tid / 9, p = tid % 9;
    const float* ins = &g_instr[(b*4+step)*HH];
    float a = 0.f;
    for (int h = 0; h < HH; h++) a += ins[h] * prop[p*HH + h];
    s[tid] = a;
    __syncthreads();
    if (p == 0) {
        float mx = -1e30f;
        for (int q = 0; q < 9; q++) mx = fmaxf(mx, s[b*9+q]);
        float e[9], sum = 0.f;
        for (int q = 0; q < 9; q++) { e[q] = expf(s[b*9+q]-mx); sum += e[q]; }
        for (int q = 0; q < 9; q++) g_psim[b*9+q] = e[q]/sum;
    }
}

__global__ void vb_k(int step) {
    int b = blockIdx.x;
    for (int j = threadIdx.x; j < K2; j += 256)
        g_vb[b*K2 + j] = g_psim[b*9 + j/HH] * g_instr[(b*4+step)*HH + j%HH];
}

// ---- tensor-core GEMM: split-bf16 x3, double-buffered, fused epilogue ----
// B planes precomputed (g_wph/l or g_weh/l); batch index uniform per block.
template<int IS_EDGE>
__global__ __launch_bounds__(512, 1)
void mma_gemm_k(const float* __restrict__ Asrc, const int* __restrict__ esrc,
                const int* __restrict__ edst, const float* __restrict__ wv, int step) {
    extern __shared__ __align__(16) char smraw[];
    __nv_bfloat16* AsH = (__nv_bfloat16*)smraw;            // [2][128][SPAD]
    __nv_bfloat16* AsL = AsH + 2*128*SPAD;
    __nv_bfloat16* BsH = AsL + 2*128*SPAD;                 // [2][NPAD][SPAD]
    __nv_bfloat16* BsL = BsH + 2*NPAD*SPAD;
    float* vbs = (float*)(BsL + 2*NPAD*SPAD);              // K2 floats (node) / NPAD (edge)

    const int KT = IS_EDGE ? 19 : 150;
    const int AK = IS_EDGE ? HH : K2;
    int tid = threadIdx.x;
    int row0 = blockIdx.x * 128;
    int b = IS_EDGE ? (row0 >> 12) : (row0 >> 9);

    if (!IS_EDGE) {
        for (int i = tid; i < K2; i += 512) vbs[i] = g_vb[b*K2 + i];
    } else {
        for (int i = tid; i < NPAD; i += 512) vbs[i] = (i < HH) ? g_instr[(b*4+step)*HH + i] : 0.f;
    }
    __syncthreads();

    const __nv_bfloat16* BgH = IS_EDGE ? g_weh : g_wph;
    const __nv_bfloat16* BgL = IS_EDGE ? g_wel : g_wpl;

    int ar = tid >> 2, ak = (tid & 3) * 4;   // A: row ar (0..127), cols ak..ak+3
    float4 a_reg;
    uint4  b_reg[3];

    auto prefetch = [&](int kt) {
        int j0 = kt * BK;
        if (!IS_EDGE || kt < KT-1 || ak < 12) {
            a_reg = *(const float4*)&Asrc[(row0 + ar)*AK + j0 + ak];
        } else {
            a_reg = make_float4(0.f, 0.f, 0.f, 0.f);
        }
        #pragma unroll
        for (int i = 0; i < 3; i++) {
            int f = tid + 512*i;
            if (f < 1216) {
                const __nv_bfloat16* src = (f < 608) ? BgH : BgL;
                int rem = (f < 608) ? f : f - 608;
                b_reg[i] = *(const uint4*)(src + j0*NPAD + rem*8);
            }
        }
    };

    auto sts = [&](int kt, int st) {
        int j0 = kt * BK;
        float4 vv = *(const float4*)&vbs[j0 + ak];
        float p0 = a_reg.x*vv.x, p1 = a_reg.y*vv.y, p2 = a_reg.z*vv.z, p3 = a_reg.w*vv.w;
        __nv_bfloat16 h0 = __float2bfloat16(p0), h1 = __float2bfloat16(p1);
        __nv_bfloat16 h2 = __float2bfloat16(p2), h3 = __float2bfloat16(p3);
        __nv_bfloat162* dH = (__nv_bfloat162*)(AsH + st*128*SPAD + ar*SPAD + ak);
        dH[0] = __halves2bfloat162(h0, h1);
        dH[1] = __halves2bfloat162(h2, h3);
        __nv_bfloat162* dL = (__nv_bfloat162*)(AsL + st*128*SPAD + ar*SPAD + ak);
        dL[0] = __floats2bfloat162_rn(p0 - __bfloat162float(h0), p1 - __bfloat162float(h1));
        dL[1] = __floats2bfloat162_rn(p2 - __bfloat162float(h2), p3 - __bfloat162float(h3));
        #pragma unroll
        for (int i = 0; i < 3; i++) {
            int f = tid + 512*i;
            if (f < 1216) {
                __nv_bfloat16* dst = (f < 608) ? BsH : BsL;
                int rem = (f < 608) ? f : f - 608;
                int n = rem >> 1, kk = (rem & 1) * 8;
                *(uint4*)(dst + st*NPAD*SPAD + n*SPAD + kk) = b_reg[i];
            }
        }
    };

    int warp = tid >> 5, lane = tid & 31;
    int wm = warp & 7, wn = warp >> 3;
    int g = lane >> 2, q = lane & 3;
    int k0 = q * 2;
    float acc[19][4];
    #pragma unroll
    for (int t = 0; t < 19; t++) { acc[t][0]=0.f; acc[t][1]=0.f; acc[t][2]=0.f; acc[t][3]=0.f; }

    prefetch(0);
    sts(0, 0);
    __syncthreads();
    for (int kt = 0; kt < KT; kt++) {
        int st = kt & 1;
        if (kt + 1 < KT) prefetch(kt + 1);
        const __nv_bfloat16* pAH = AsH + st*128*SPAD;
        const __nv_bfloat16* pAL = AsL + st*128*SPAD;
        const __nv_bfloat16* pBH = BsH + st*NPAD*SPAD;
        const __nv_bfloat16* pBL = BsL + st*NPAD*SPAD;
        int r = wm*16 + g;
        unsigned ah[4], al[4];
        ah[0] = *(const unsigned*)(pAH + r*SPAD + k0);
        ah[1] = *(const unsigned*)(pAH + (r+8)*SPAD + k0);
        ah[2] = *(const unsigned*)(pAH + r*SPAD + k0 + 8);
        ah[3] = *(const unsigned*)(pAH + (r+8)*SPAD + k0 + 8);
        al[0] = *(const unsigned*)(pAL + r*SPAD + k0);
        al[1] = *(const unsigned*)(pAL + (r+8)*SPAD + k0);
        al[2] = *(const unsigned*)(pAL + r*SPAD + k0 + 8);
        al[3] = *(const unsigned*)(pAL + (r+8)*SPAD + k0 + 8);
        #pragma unroll
        for (int t = 0; t < 19; t++) {
            int n = wn*152 + t*8 + g;
            unsigned bh[2], bl[2];
            bh[0] = *(const unsigned*)(pBH + n*SPAD + k0);
            bh[1] = *(const unsigned*)(pBH + n*SPAD + k0 + 8);
            bl[0] = *(const unsigned*)(pBL + n*SPAD + k0);
            bl[1] = *(const unsigned*)(pBL + n*SPAD + k0 + 8);
            mma16816(acc[t], ah, bh);
            mma16816(acc[t], ah, bl);
            mma16816(acc[t], al, bh);
        }
        __syncthreads();
        if (kt + 1 < KT) { sts(kt+1, (kt+1) & 1); __syncthreads(); }
    }

    // epilogue: elu, dot with wv over columns, reduce over quad, atomic per row
    float pa = 0.f, pb = 0.f;
    #pragma unroll
    for (int t = 0; t < 19; t++) {
        int c0 = wn*152 + t*8 + q*2;
        #pragma unroll
        for (int jj = 0; jj < 2; jj++) {
            int c = c0 + jj;
            if (c < HH) {
                float w = wv[c];
                float v0 = acc[t][jj];     v0 = v0 > 0.f ? v0 : expm1f(v0);
                float v1 = acc[t][2+jj];   v1 = v1 > 0.f ? v1 : expm1f(v1);
                pa += v0 * w;
                pb += v1 * w;
            }
        }
    }
    pa += __shfl_xor_sync(0xffffffffu, pa, 1);
    pa += __shfl_xor_sync(0xffffffffu, pa, 2);
    pb += __shfl_xor_sync(0xffffffffu, pb, 1);
    pb += __shfl_xor_sync(0xffffffffu, pb, 2);
    if (q == 0) {
        int rA = row0 + wm*16 + g;
        int rB = rA + 8;
        if (!IS_EDGE) {
            atomicAdd(&g_nsl[rA], pa);
            atomicAdd(&g_nsl[rB], pb);
        } else {
            atomicAdd(&g_nrl[edst[rA]], g_dist[esrc[rA]] * pa);
            atomicAdd(&g_nrl[edst[rB]], g_dist[esrc[rB]] * pb);
        }
    }
}

__global__ void seg_softmax_k() {
    __shared__ float red[NPG];
    int b = blockIdx.x, t = threadIdx.x;   // 512 threads
    int n = b*NPG + t;
    float v1 = g_nsl[n], v2 = g_nrl[n];
    red[t] = v1; __syncthreads();
    for (int s = 256; s > 0; s >>= 1) { if (t < s) red[t] = fmaxf(red[t], red[t+s]); __syncthreads(); }
    float m1 = red[0]; __syncthreads();
    float e1 = expf(v1 - m1);
    red[t] = e1; __syncthreads();
    for (int s = 256; s > 0; s >>= 1) { if (t < s) red[t] += red[t+s]; __syncthreads(); }
    float s1 = red[0]; __syncthreads();
    red[t] = v2; __syncthreads();
    for (int s = 256; s > 0; s >>= 1) { if (t < s) red[t] = fmaxf(red[t], red[t+s]); __syncthreads(); }
    float m2 = red[0]; __syncthreads();
    float e2 = expf(v2 - m2);
    red[t] = e2; __syncthreads();
    for (int s = 256; s > 0; s >>= 1) { if (t < s) red[t] += red[t+s]; __syncthreads(); }
    float s2 = red[0]; __syncthreads();
    float rs = g_psim[b*9 + 8];
    g_dist[n] = rs * (e2/s2) + (1.f - rs) * (e1/s1);
}

__global__ void agg_k(const float* __restrict__ attrs) {
    int b = blockIdx.x, ch = blockIdx.y, h = threadIdx.x;  // 300 threads, y=8 chunks
    __shared__ float np[8];
    if (h < 8) np[h] = g_psim[b*9 + h];
    __syncthreads();
    float acc = 0.f;
    int nbase = b*NPG + ch*(NPG/8);
    for (int nn = 0; nn < NPG/8; nn++) {
        int n = nbase + nn;
        float d = g_dist[n], w = 0.f;
        #pragma unroll
        for (int p = 0; p < 8; p++) w += np[p] * attrs[(n*PP + p)*HH + h];
        acc += d * w;
    }
    atomicAdd(&g_agg[b*HH + h], acc);
}

__global__ void fc1_k(const float* __restrict__ fc1b) {
    int b = blockIdx.x, j = threadIdx.x;   // 600 threads
    __shared__ float fs[600];
    fs[j] = (j < HH) ? g_h[b*HH + j] : g_agg[b*HH + (j - HH)];
    __syncthreads();
    float a = fc1b[j];
    #pragma unroll 4
    for (int k = 0; k < 600; k++) a += g_fc1T[k*600 + j] * fs[k];
    g_feat1[b*600 + j] = eluf(a);
}

__global__ void fc2_k(const float* __restrict__ fc2b, float* __restrict__ out) {
    int b = blockIdx.x, t = threadIdx.x;   // 256 threads, y=8
    __shared__ float f1[600];
    for (int k = t; k < 600; k += 256) f1[k] = g_feat1[b*600 + k];
    __syncthreads();
    int o = blockIdx.y*256 + t;
    if (o < OUTD) {
        float a = fc2b[o];
        #pragma unroll 4
        for (int k = 0; k < 600; k++) a += g_fc2T[k*OUTD + o] * f1[k];
        out[b*OUTD + o] = a;
    }
}

extern "C" void kernel_launch(void* const* d_in, const int* in_sizes, int n_in,
                              void* d_out, int out_size) {
    (void)in_sizes; (void)n_in; (void)out_size;
    const float* questions  = (const float*)d_in[0];
    const float* cvocab     = (const float*)d_in[1];
    const float* prop       = (const float*)d_in[2];
    const float* node_attrs = (const float*)d_in[3];
    const float* edge_attrs = (const float*)d_in[4];
    const float* w_tag      = (const float*)d_in[5];
    const float* demb       = (const float*)d_in[6];
    const float* lstm_Wih   = (const float*)d_in[7];
    const float* lstm_Whh   = (const float*)d_in[8];
    const float* lstm_bih   = (const float*)d_in[9];
    const float* lstm_bhh   = (const float*)d_in[10];
    const float* rnn_Wih    = (const float*)d_in[11];
    const float* rnn_Whh    = (const float*)d_in[12];
    const float* rnn_bih    = (const float*)d_in[13];
    const float* rnn_bhh    = (const float*)d_in[14];
    const float* Wp         = (const float*)d_in[15];
    const float* We         = (const float*)d_in[16];
    const float* w_ns       = (const float*)d_in[17];
    const float* w_rs       = (const float*)d_in[18];
    const float* fc1_w      = (const float*)d_in[19];
    const float* fc1_b      = (const float*)d_in[20];
    const float* fc2_w      = (const float*)d_in[21];
    const float* fc2_b      = (const float*)d_in[22];
    const int*   nidx       = (const int*)d_in[23];
    const int*   esrc       = (const int*)d_in[24];
    const int*   edst       = (const int*)d_in[25];
    const int*   ebatch     = (const int*)d_in[26];
    (void)ebatch;
    float* out = (float*)d_out;

    void *vp;
    cudaGetSymbolAddress(&vp, g_qw);     float* p_qw    = (float*)vp;
    cudaGetSymbolAddress(&vp, g_logits); float* p_logits= (float*)vp;
    cudaGetSymbolAddress(&vp, g_vocab);  float* p_vocab = (float*)vp;
    cudaGetSymbolAddress(&vp, g_tagged); float* p_tagged= (float*)vp;
    cudaGetSymbolAddress(&vp, g_xw);     float* p_xw    = (float*)vp;
    cudaGetSymbolAddress(&vp, g_WihT);   float* p_WihT  = (float*)vp;
    cudaGetSymbolAddress(&vp, g_WhhT);   float* p_WhhT  = (float*)vp;
    cudaGetSymbolAddress(&vp, g_rWihT);  float* p_rWihT = (float*)vp;
    cudaGetSymbolAddress(&vp, g_rWhhT);  float* p_rWhhT = (float*)vp;
    cudaGetSymbolAddress(&vp, g_fc1T);   float* p_fc1T  = (float*)vp;
    cudaGetSymbolAddress(&vp, g_fc2T);   float* p_fc2T  = (float*)vp;

    cudaFuncSetAttribute(mma_gemm_k<0>, cudaFuncAttributeMaxDynamicSharedMemorySize, SMEM_MMA);
    cudaFuncSetAttribute(mma_gemm_k<1>, cudaFuncAttributeMaxDynamicSharedMemorySize, SMEM_MMA);

    transpose_k<<<(H4*HH+255)/256, 256>>>(lstm_Wih, p_WihT, H4, HH);
    transpose_k<<<(H4*HH+255)/256, 256>>>(lstm_Whh, p_WhhT, H4, HH);
    transpose_k<<<(HH*HH+255)/256, 256>>>(rnn_Wih,  p_rWihT, HH, HH);
    transpose_k<<<(HH*HH+255)/256, 256>>>(rnn_Whh,  p_rWhhT, HH, HH);
    transpose_k<<<(600*600+255)/256, 256>>>(fc1_w, p_fc1T, 600, 600);
    transpose_k<<<(OUTD*600+255)/256, 256>>>(fc2_w, p_fc2T, OUTD, 600);
    copy_vocab_k<<<(CE*HH+255)/256, 256>>>(cvocab, demb);
    init_zero_k<<<(BB*HH+255)/256, 256>>>();
    count_k<<<(NND+255)/256, 256>>>(nidx);
    dist_init_k<<<(NND+255)/256, 256>>>(nidx);
    split_wp_k<<<(K2*NPAD+255)/256, 256>>>(Wp);
    split_we_k<<<(NPAD*NPAD+255)/256, 256>>>(We);

    // tagging
    gemm_t<0><<<dim3((HH+63)/64, ML/64), 256>>>(questions, w_tag, p_qw, ML, HH, HH, HH, HH, HH);
    gemm_t<1><<<dim3((CE+63)/64, ML/64), 256>>>(p_qw, p_vocab, p_logits, ML, CE, HH, HH, HH, CE);
    softmax_rows_k<<<ML, 256>>>();
    gemm_t<0><<<dim3((HH+63)/64, ML/64), 256>>>(p_logits, cvocab, p_tagged, ML, HH, CCD, CE, HH, HH);
    tagged_adj_k<<<(ML*HH+255)/256, 256>>>(questions);

    // LSTM encoder
    gemm_t<0><<<dim3((H4+63)/64, ML/64), 256>>>(p_tagged, p_WihT, p_xw, ML, H4, HH, HH, H4, H4);
    for (int t = 0; t < LL; t++) lstm_step_k<<<BB, 600>>>(lstm_bih, lstm_bhh, t);

    // RNN decoder + attention
    rnn_ew_k<<<BB, HH>>>();
    for (int s = 0; s < 4; s++) rnn_step_k<<<BB, HH>>>(rnn_bih, rnn_bhh, s);
    attn_k<<<dim3(BB, 4), 128>>>();

    // message passing steps (tensor-core GEMMs)
    for (int s = 0; s < 3; s++) {
        psim_k<<<1, BB*9>>>(prop, s);
        vb_k<<<BB, 256>>>(s);
        zero_nl_k<<<(NND+255)/256, 256>>>();
        mma_gemm_k<0><<<NND/128, 512, SMEM_MMA>>>(node_attrs, esrc, edst, w_ns, s);
        mma_gemm_k<1><<<EED/128, 512, SMEM_MMA>>>(edge_attrs, esrc, edst, w_rs, s);
        seg_softmax_k<<<BB, NPG>>>();
    }

    // final aggregation + head
    psim_k<<<1, BB*9>>>(prop, 3);
    agg_k<<<dim3(BB, 8), HH>>>(node_attrs);
    fc1_k<<<BB, 600>>>(fc1_b);
    fc2_k<<<dim3(BB, 8), 256>>>(fc2_b, out);
}